// round 16
// baseline (speedup 1.0000x reference)
#include <cuda_runtime.h>
#include <cuda_fp16.h>
#include <cstdint>
#include <mma.h>
#include <math.h>

using namespace nvcuda;

// ---------------------------------------------------------------------------
// WindowAttentionV2: b=4096 windows, n=64 tokens, C=384, H=12 heads, d=32
// ---------------------------------------------------------------------------

#define BWIN   4096
#define NTOK   64
#define CDIM   384
#define HEADS  12
#define HDIM   32
#define NWIN   1024
#define M1     (BWIN * NTOK)          // 262144 rows
#define QKV_N  (3 * CDIM)             // 1152
#define QKV_STRIDE (BWIN * HEADS * NTOK * HDIM)

// Scratch (device globals; no allocations allowed)
__device__ __half g_qkv[3ll * QKV_STRIDE];          // fp16 [3][b][h][n][d] (no bias)
__device__ __half g_att[(long long)M1 * CDIM];      // fp16 attention output
__device__ __half g_xh[(long long)M1 * CDIM];       // fp16 copy of x
__device__ __half g_wh[CDIM * QKV_N];               // fp16 copy of qkv_w
__device__ __half g_wph[CDIM * CDIM];               // fp16 copy of proj_w
__device__ float  g_hidden[4096 * 512];             // cpb hidden layer
__device__ float  g_tab[4096 * HEADS];
__device__ float  g_bias[HEADS * NTOK * NTOK];
__device__ float  g_bm[(long long)HEADS * NWIN * NTOK * NTOK];  // bias+mask, 192MB

// ---------------------------------------------------------------------------
// Packed f32x2 helpers (sm_103a FFMA2 path — only reachable via PTX f32x2)
// ---------------------------------------------------------------------------
__device__ __forceinline__ unsigned long long pk2(float lo, float hi)
{
    unsigned long long r;
    asm("mov.b64 %0, {%1, %2};" : "=l"(r) : "r"(__float_as_uint(lo)), "r"(__float_as_uint(hi)));
    return r;
}
__device__ __forceinline__ float upk_sum(unsigned long long v)
{
    unsigned int lo, hi;
    asm("mov.b64 {%0, %1}, %2;" : "=r"(lo), "=r"(hi) : "l"(v));
    return __uint_as_float(lo) + __uint_as_float(hi);
}
#define FMA2(d, a, b, c) \
    asm("fma.rn.f32x2 %0, %1, %2, %3;" : "=l"(d) : "l"(a), "l"(b), "l"(c))

// Packed fp16 exp2: one MUFU.EX2.F16x2 evaluates two exponentials.
__device__ __forceinline__ float2 exp2_pair_h2(float ya, float yc)
{
    __half2 h = __floats2half2_rn(ya, yc);
    unsigned u = *reinterpret_cast<unsigned*>(&h);
    unsigned v;
    asm("ex2.approx.f16x2 %0, %1;" : "=r"(v) : "r"(u));
    __half2 r = *reinterpret_cast<__half2*>(&v);
    return __half22float2(r);
}

// ---------------------------------------------------------------------------
// CPB: hidden layer (4096x512 elementwise), then 4096x12 dot products
// ---------------------------------------------------------------------------
__global__ __launch_bounds__(256) void cpb_hidden_kernel(const float* __restrict__ table,
                                                         const float* __restrict__ w1,
                                                         const float* __restrict__ b1)
{
    int idx = blockIdx.x * blockDim.x + threadIdx.x;
    if (idx >= 4096 * 512) return;
    int i = idx >> 9;
    int j = idx & 511;
    float t0 = table[i * 2 + 0];
    float t1 = table[i * 2 + 1];
    g_hidden[idx] = fmaxf(fmaf(t0, w1[j], fmaf(t1, w1[512 + j], b1[j])), 0.f);
}

__global__ __launch_bounds__(256) void cpb_out_kernel(const float* __restrict__ w2)
{
    int e = blockIdx.x * blockDim.x + threadIdx.x;
    if (e >= 4096 * HEADS) return;
    int i = e / HEADS;
    int h = e - i * HEADS;
    const float* hid = &g_hidden[i * 512];
    float acc = 0.f;
    #pragma unroll 8
    for (int j = 0; j < 512; j++) acc += hid[j] * w2[j * HEADS + h];
    g_tab[e] = acc;
}

__global__ void cpb_gather_kernel(const int* __restrict__ index)
{
    int e = blockIdx.x * blockDim.x + threadIdx.x;
    if (e >= HEADS * 4096) return;
    int h = e / 4096;
    int qk = e % 4096;
    float v = g_tab[index[qk] * HEADS + h];
    g_bias[e] = 16.f / (1.f + expf(-v));
}

// bm[h][w][qk] = g_bias[h][qk] + mask[w][qk]
__global__ __launch_bounds__(256) void bm_combine_kernel(const float* __restrict__ mask)
{
    long long i = (long long)blockIdx.x * blockDim.x + threadIdx.x;   // float4 idx
    if (i >= (long long)HEADS * NWIN * 4096 / 4) return;
    long long f = i * 4;
    int h   = (int)(f >> 22);
    int w   = (int)((f >> 12) & (NWIN - 1));
    int qk4 = (int)(f & 4095);
    float4 bv = *(const float4*)&g_bias[h * 4096 + qk4];
    float4 mv = *(const float4*)&mask[(long long)w * 4096 + qk4];
    float4 o = make_float4(bv.x + mv.x, bv.y + mv.y, bv.z + mv.z, bv.w + mv.w);
    *(float4*)&g_bm[f] = o;
}

// ---------------------------------------------------------------------------
// fp32 -> fp16 converters
// ---------------------------------------------------------------------------
__global__ __launch_bounds__(256) void convert_x_kernel(const float* __restrict__ x)
{
    long long n4 = (long long)M1 * CDIM / 4;
    long long stride = (long long)gridDim.x * blockDim.x;
    for (long long i = blockIdx.x * blockDim.x + threadIdx.x; i < n4; i += stride) {
        float4 v = ((const float4*)x)[i];
        __half2* dst = (__half2*)g_xh;
        dst[2 * i + 0] = __floats2half2_rn(v.x, v.y);
        dst[2 * i + 1] = __floats2half2_rn(v.z, v.w);
    }
}

__global__ __launch_bounds__(256) void convert_w_kernel(const float* __restrict__ w,
                                                        int n4, __half* dst_h)
{
    int i = blockIdx.x * blockDim.x + threadIdx.x;
    if (i >= n4) return;
    float4 v = ((const float4*)w)[i];
    __half2* dst = (__half2*)dst_h;
    dst[2 * i + 0] = __floats2half2_rn(v.x, v.y);
    dst[2 * i + 1] = __floats2half2_rn(v.z, v.w);
}

// ---------------------------------------------------------------------------
// fp16 GEMM cores: 128x128 tile, BK=32, 4-stage cp.async ring, fp32 accum.
// ---------------------------------------------------------------------------
#define HBK 32
#define HAPAD 40
#define HBPAD 136
#define HAS_STAGE (128 * HAPAD)
#define HBS_STAGE (HBK * HBPAD)
#define HSTAGES 4
#define HGEMM_SMEM_BYTES (HSTAGES * (HAS_STAGE + HBS_STAGE) * 2)   // 75776

__device__ __forceinline__ void cp16(void* s, const void* g)
{
    unsigned int sa = (unsigned int)__cvta_generic_to_shared(s);
    asm volatile("cp.async.cg.shared.global [%0], [%1], 16;\n" :: "r"(sa), "l"(g));
}

// qkv: A = g_xh, B = g_wh, N=1152; fp16 epilogue store into g_qkv
__global__ __launch_bounds__(256)
void hgemm_qkv()
{
    extern __shared__ __half hsm[];
    __half* As = hsm;
    __half* Bs = hsm + HSTAGES * HAS_STAGE;

    const int N = QKV_N, K = CDIM;
    int tid  = threadIdx.x;
    int lane = tid & 31;
    int warp = tid >> 5;
    int wm = warp >> 1;
    int wn = warp & 1;
    long long crow = (long long)blockIdx.y * 128;
    int ccol = blockIdx.x * 128;

    int ar[2], ac[2], br[2], bc[2];
    #pragma unroll
    for (int s = 0; s < 2; s++) {
        int i = tid + s * 256;
        ar[s] = i >> 2;  ac[s] = (i & 3) * 8;
        br[s] = i >> 4;  bc[s] = (i & 15) * 8;
    }

    wmma::fragment<wmma::accumulator, 16, 16, 16, float> acc[2][4];
    #pragma unroll
    for (int i = 0; i < 2; i++)
        #pragma unroll
        for (int j = 0; j < 4; j++) wmma::fill_fragment(acc[i][j], 0.f);

    const int NK = K / HBK;   // 12

    auto issue = [&](int buf, int kt) {
        int k0 = kt * HBK;
        #pragma unroll
        for (int s = 0; s < 2; s++) {
            cp16(&As[buf * HAS_STAGE + ar[s] * HAPAD + ac[s]],
                 g_xh + (crow + ar[s]) * K + k0 + ac[s]);
            cp16(&Bs[buf * HBS_STAGE + br[s] * HBPAD + bc[s]],
                 g_wh + (long long)(k0 + br[s]) * N + ccol + bc[s]);
        }
        asm volatile("cp.async.commit_group;\n");
    };

    issue(0, 0); issue(1, 1); issue(2, 2);

    for (int kt = 0; kt < NK; kt++) {
        if (kt <= NK - 3)      asm volatile("cp.async.wait_group 2;\n");
        else if (kt == NK - 2) asm volatile("cp.async.wait_group 1;\n");
        else                   asm volatile("cp.async.wait_group 0;\n");
        __syncthreads();
        if (kt + 3 < NK) issue((kt + 3) & 3, kt + 3);

        int buf = kt & 3;
        __half* Ab = &As[buf * HAS_STAGE];
        __half* Bb = &Bs[buf * HBS_STAGE];
        #pragma unroll
        for (int kk = 0; kk < HBK; kk += 16) {
            wmma::fragment<wmma::matrix_a, 16, 16, 16, __half, wmma::row_major> af[2];
            wmma::fragment<wmma::matrix_b, 16, 16, 16, __half, wmma::row_major> bf[4];
            #pragma unroll
            for (int i = 0; i < 2; i++)
                wmma::load_matrix_sync(af[i], &Ab[(wm * 32 + i * 16) * HAPAD + kk], HAPAD);
            #pragma unroll
            for (int j = 0; j < 4; j++)
                wmma::load_matrix_sync(bf[j], &Bb[kk * HBPAD + wn * 64 + j * 16], HBPAD);
            #pragma unroll
            for (int i = 0; i < 2; i++)
                #pragma unroll
                for (int j = 0; j < 4; j++)
                    wmma::mma_sync(acc[i][j], af[i], bf[j], acc[i][j]);
        }
    }

    // fp16 epilogue via per-warp smem patch (stage buffers are dead)
    __syncthreads();
    float* ep = ((float*)hsm) + warp * 256;
    #pragma unroll
    for (int i = 0; i < 2; i++) {
        long long m0 = crow + wm * 32 + i * 16;
        int b  = (int)(m0 >> 6);
        int n0 = (int)(m0 & 63);
        #pragma unroll
        for (int j = 0; j < 4; j++) {
            int c0 = ccol + wn * 64 + j * 16;
            int three = c0 / CDIM;
            int rem   = c0 - three * CDIM;
            int head  = rem >> 5;
            int dd0   = rem & 31;
            long long off = (long long)three * QKV_STRIDE +
                            (((long long)(b * HEADS + head)) * NTOK + n0) * HDIM + dd0;
            wmma::store_matrix_sync(ep, acc[i][j], 16, wmma::mem_row_major);
            __syncwarp();
            #pragma unroll
            for (int e = 0; e < 4; e++) {
                int idx = lane + e * 32;          // 0..127 pair index
                int r  = idx >> 3;                // 0..15
                int c2 = idx & 7;                 // 0..7 pairs
                float2 v = ((const float2*)ep)[idx];
                *(__half2*)&g_qkv[off + r * HDIM + 2 * c2] =
                    __floats2half2_rn(v.x, v.y);
            }
            __syncwarp();
        }
    }
}

// proj: A = g_att (half), B = g_wph, N=384; +bias, fp32 dense out
__global__ __launch_bounds__(256)
void hgemm_proj(const float* __restrict__ bias, float* __restrict__ Cout)
{
    extern __shared__ __half hsm[];
    __half* As = hsm;
    __half* Bs = hsm + HSTAGES * HAS_STAGE;

    const int N = CDIM, K = CDIM;
    int tid  = threadIdx.x;
    int lane = tid & 31;
    int warp = tid >> 5;
    int wm = warp >> 1;
    int wn = warp & 1;
    long long crow = (long long)blockIdx.y * 128;
    int ccol = blockIdx.x * 128;

    int ar[2], ac[2], br[2], bc[2];
    #pragma unroll
    for (int s = 0; s < 2; s++) {
        int i = tid + s * 256;
        ar[s] = i >> 2;  ac[s] = (i & 3) * 8;
        br[s] = i >> 4;  bc[s] = (i & 15) * 8;
    }

    wmma::fragment<wmma::accumulator, 16, 16, 16, float> acc[2][4];
    #pragma unroll
    for (int i = 0; i < 2; i++)
        #pragma unroll
        for (int j = 0; j < 4; j++) wmma::fill_fragment(acc[i][j], 0.f);

    const int NK = K / HBK;

    auto issue = [&](int buf, int kt) {
        int k0 = kt * HBK;
        #pragma unroll
        for (int s = 0; s < 2; s++) {
            cp16(&As[buf * HAS_STAGE + ar[s] * HAPAD + ac[s]],
                 g_att + (crow + ar[s]) * K + k0 + ac[s]);
            cp16(&Bs[buf * HBS_STAGE + br[s] * HBPAD + bc[s]],
                 g_wph + (long long)(k0 + br[s]) * N + ccol + bc[s]);
        }
        asm volatile("cp.async.commit_group;\n");
    };

    issue(0, 0); issue(1, 1); issue(2, 2);

    for (int kt = 0; kt < NK; kt++) {
        if (kt <= NK - 3)      asm volatile("cp.async.wait_group 2;\n");
        else if (kt == NK - 2) asm volatile("cp.async.wait_group 1;\n");
        else                   asm volatile("cp.async.wait_group 0;\n");
        __syncthreads();
        if (kt + 3 < NK) issue((kt + 3) & 3, kt + 3);

        int buf = kt & 3;
        __half* Ab = &As[buf * HAS_STAGE];
        __half* Bb = &Bs[buf * HBS_STAGE];
        #pragma unroll
        for (int kk = 0; kk < HBK; kk += 16) {
            wmma::fragment<wmma::matrix_a, 16, 16, 16, __half, wmma::row_major> af[2];
            wmma::fragment<wmma::matrix_b, 16, 16, 16, __half, wmma::row_major> bf[4];
            #pragma unroll
            for (int i = 0; i < 2; i++)
                wmma::load_matrix_sync(af[i], &Ab[(wm * 32 + i * 16) * HAPAD + kk], HAPAD);
            #pragma unroll
            for (int j = 0; j < 4; j++)
                wmma::load_matrix_sync(bf[j], &Bb[kk * HBPAD + wn * 64 + j * 16], HBPAD);
            #pragma unroll
            for (int i = 0; i < 2; i++)
                #pragma unroll
                for (int j = 0; j < 4; j++)
                    wmma::mma_sync(acc[i][j], af[i], bf[j], acc[i][j]);
        }
    }

    __syncthreads();
    float* ep = ((float*)hsm) + warp * 256;
    #pragma unroll
    for (int i = 0; i < 2; i++) {
        #pragma unroll
        for (int j = 0; j < 4; j++) {
            wmma::store_matrix_sync(ep, acc[i][j], 16, wmma::mem_row_major);
            __syncwarp();
            long long m0 = crow + wm * 32 + i * 16;
            int c0 = ccol + wn * 64 + j * 16;
            #pragma unroll
            for (int e = 0; e < 8; e++) {
                int idx = lane + e * 32;
                int r = idx >> 4;
                int c = idx & 15;
                Cout[(m0 + r) * N + c0 + c] = ep[idx] + bias[c0 + c];
            }
            __syncwarp();
        }
    }
}

// ---------------------------------------------------------------------------
// Fused attention — R13 internals exactly; blockIdx remapped so the FOUR
// blocks sharing one bm row (b = w, w+1024, w+2048, w+3072 at head h) are
// CONSECUTIVE in launch order -> bm row hits L2 three times out of four.
// ---------------------------------------------------------------------------
#define QKS 34
#define SCS 68

__global__ __launch_bounds__(256)
void attn_kernel(const float* __restrict__ logit_scale,
                 const float* __restrict__ qkv_b)
{
    // remap: bid = ((h*NWIN + w) << 2) | wi ; b = w + wi*NWIN
    int bid = blockIdx.x;
    int wi  = bid & 3;
    int hw  = bid >> 2;               // 0 .. HEADS*NWIN-1
    int h   = hw / NWIN;
    int w   = hw - h * NWIN;
    int b   = w + wi * NWIN;
    int bh  = b * HEADS + h;

    __shared__ float qs[64 * QKS];
    __shared__ float ks[64 * QKS];
    __shared__ float vs[64 * 33];
    __shared__ float sc[64 * SCS];
    __shared__ float rq[64];
    __shared__ float rk[64];

    int tid  = threadIdx.x;
    int warp = tid >> 5;
    int lane = tid & 31;
    int tr = tid >> 4;
    int tc = tid & 15;

    const __half* qg = g_qkv + (long long)bh * (NTOK * HDIM);
    const __half* kg = qg + QKV_STRIDE;
    const __half* vg = kg + QKV_STRIDE;

    const float* bmrow = g_bm + ((long long)h * NWIN + w) * 4096;

    // stream bias+mask row into sc (coalesced float4; latency overlapped)
    #pragma unroll
    for (int k = 0; k < 4; k++) {
        int e4 = tid + k * 256;          // float4 index 0..1023
        int qi  = e4 >> 4;
        int kj4 = (e4 & 15) * 4;
        float4 v = ((const float4*)bmrow)[e4];
        *(float4*)&sc[qi * SCS + kj4] = v;
    }

    // per-thread column-group biases: 8 columns starting at cb
    int cb = (tid & 3) * 8;
    float bq8[8], bk8[8], bv8[8];
    #pragma unroll
    for (int t = 0; t < 8; t++) {
        bq8[t] = qkv_b[h * HDIM + cb + t];
        bk8[t] = qkv_b[CDIM + h * HDIM + cb + t];
        bv8[t] = qkv_b[2 * CDIM + h * HDIM + cb + t];
    }

    {
        int e = tid;               // 0..255 : 16B (8 halves) per tensor
        int r = e >> 2;            // row 0..63
        int c = (e & 3) * 8;       // col 0,8,16,24
        uint4 qraw = ((const uint4*)qg)[e];
        uint4 kraw = ((const uint4*)kg)[e];
        uint4 vraw = ((const uint4*)vg)[e];
        const __half2* qh = (const __half2*)&qraw;
        const __half2* kh = (const __half2*)&kraw;
        const __half2* vh = (const __half2*)&vraw;
        float* dq = &qs[r * QKS + c];
        float* dk = &ks[r * QKS + c];
        float* dv = &vs[r * 33 + c];
        #pragma unroll
        for (int t = 0; t < 4; t++) {
            float2 qf = __half22float2(qh[t]);
            float2 kf = __half22float2(kh[t]);
            float2 vf = __half22float2(vh[t]);
            dq[2 * t]     = qf.x + bq8[2 * t];
            dq[2 * t + 1] = qf.y + bq8[2 * t + 1];
            dk[2 * t]     = kf.x + bk8[2 * t];
            dk[2 * t + 1] = kf.y + bk8[2 * t + 1];
            dv[2 * t]     = vf.x + bv8[2 * t];
            dv[2 * t + 1] = vf.y + bv8[2 * t + 1];
        }
    }
    __syncthreads();

    // per-row inverse norms (no element writeback)
    #pragma unroll
    for (int i = 0; i < 16; i++) {
        int r = warp * 16 + i;
        const float* buf = (r < 64) ? &qs[r * QKS] : &ks[(r - 64) * QKS];
        float v = buf[lane];
        float ss = v * v;
        #pragma unroll
        for (int o = 16; o; o >>= 1) ss += __shfl_xor_sync(~0u, ss, o);
        if (lane == 0) {
            float inv = 1.f / fmaxf(sqrtf(ss), 1e-12f);
            if (r < 64) rq[r] = inv; else rk[r - 64] = inv;
        }
    }
    __syncthreads();

    float scale = expf(fminf(logit_scale[h], 4.60517018598809f)); // ln(100)

    // scores: 4x4 register tile, packed f32x2 FMA along l; bm base in sc
    {
        unsigned long long acc2[4][4];
        #pragma unroll
        for (int i = 0; i < 4; i++)
            #pragma unroll
            for (int j = 0; j < 4; j++) acc2[i][j] = 0ull;
        #pragma unroll 4
        for (int l2 = 0; l2 < 16; l2++) {
            unsigned long long qv[4], kv[4];
            #pragma unroll
            for (int i = 0; i < 4; i++)
                qv[i] = *(const unsigned long long*)&qs[(tr + 16 * i) * QKS + 2 * l2];
            #pragma unroll
            for (int j = 0; j < 4; j++)
                kv[j] = *(const unsigned long long*)&ks[(tc + 16 * j) * QKS + 2 * l2];
            #pragma unroll
            for (int i = 0; i < 4; i++)
                #pragma unroll
                for (int j = 0; j < 4; j++)
                    FMA2(acc2[i][j], qv[i], kv[j], acc2[i][j]);
        }
        #pragma unroll
        for (int i = 0; i < 4; i++) {
            int qi = tr + 16 * i;
            float si = scale * rq[qi];
            #pragma unroll
            for (int j = 0; j < 4; j++) {
                int kj = tc + 16 * j;
                float s = si * rk[kj];
                float base = sc[qi * SCS + kj];
                sc[qi * SCS + kj] = fmaf(upk_sum(acc2[i][j]), s, base);
            }
        }
    }
    __syncthreads();

    // softmax: warp per 8 rows; exp via packed fp16 MUFU (2 exps / MUFU)
    {
        const float L2E = 1.44269504088896f;
        #pragma unroll
        for (int i = 0; i < 8; i++) {
            int qi = warp * 8 + i;
            float a = sc[qi * SCS + lane];
            float c = sc[qi * SCS + 32 + lane];
            float mx = fmaxf(a, c);
            #pragma unroll
            for (int o = 16; o; o >>= 1) mx = fmaxf(mx, __shfl_xor_sync(~0u, mx, o));
            float2 e = exp2_pair_h2((a - mx) * L2E, (c - mx) * L2E);
            float sm = e.x + e.y;
            #pragma unroll
            for (int o = 16; o; o >>= 1) sm += __shfl_xor_sync(~0u, sm, o);
            float inv = 1.f / sm;
            sc[qi * SCS + lane]      = e.x * inv;
            sc[qi * SCS + 32 + lane] = e.y * inv;
        }
    }
    __syncthreads();

    // PV: 4x2 register tile, packed f32x2 FMA along kj
    {
        unsigned long long acc2[4][2];
        #pragma unroll
        for (int i = 0; i < 4; i++) { acc2[i][0] = 0ull; acc2[i][1] = 0ull; }
        #pragma unroll 4
        for (int kj2 = 0; kj2 < 32; kj2++) {
            unsigned long long pv[4];
            #pragma unroll
            for (int i = 0; i < 4; i++)
                pv[i] = *(const unsigned long long*)&sc[(tr + 16 * i) * SCS + 2 * kj2];
            unsigned long long vv0 = pk2(vs[(2 * kj2) * 33 + tc],
                                         vs[(2 * kj2 + 1) * 33 + tc]);
            unsigned long long vv1 = pk2(vs[(2 * kj2) * 33 + tc + 16],
                                         vs[(2 * kj2 + 1) * 33 + tc + 16]);
            #pragma unroll
            for (int i = 0; i < 4; i++) {
                FMA2(acc2[i][0], pv[i], vv0, acc2[i][0]);
                FMA2(acc2[i][1], pv[i], vv1, acc2[i][1]);
            }
        }
        #pragma unroll
        for (int i = 0; i < 4; i++) {
            int qi = tr + 16 * i;
            long long rowo = ((long long)b * NTOK + qi) * CDIM + h * HDIM;
            g_att[rowo + tc]      = __float2half_rn(upk_sum(acc2[i][0]));
            g_att[rowo + tc + 16] = __float2half_rn(upk_sum(acc2[i][1]));
        }
    }
}

// ---------------------------------------------------------------------------
extern "C" void kernel_launch(void* const* d_in, const int* in_sizes, int n_in,
                              void* d_out, int out_size)
{
    const float* x           = (const float*)d_in[0];
    const float* mask        = (const float*)d_in[1];
    const float* qkv_w       = (const float*)d_in[2];
    const float* qkv_b       = (const float*)d_in[3];
    const float* proj_w      = (const float*)d_in[4];
    const float* proj_b      = (const float*)d_in[5];
    const float* logit_scale = (const float*)d_in[6];
    const float* cpb_w1      = (const float*)d_in[7];
    const float* cpb_b1      = (const float*)d_in[8];
    const float* cpb_w2      = (const float*)d_in[9];
    const float* rel_table   = (const float*)d_in[10];
    const int*   rel_index   = (const int*)d_in[11];
    float* out = (float*)d_out;

    static int attr_done = 0;
    static cudaStream_t s2;
    static cudaEvent_t evFork, evJoin;
    if (!attr_done) {
        cudaFuncSetAttribute(hgemm_qkv,  cudaFuncAttributeMaxDynamicSharedMemorySize, HGEMM_SMEM_BYTES);
        cudaFuncSetAttribute(hgemm_proj, cudaFuncAttributeMaxDynamicSharedMemorySize, HGEMM_SMEM_BYTES);
        cudaStreamCreateWithFlags(&s2, cudaStreamNonBlocking);
        cudaEventCreateWithFlags(&evFork, cudaEventDisableTiming);
        cudaEventCreateWithFlags(&evJoin, cudaEventDisableTiming);
        attr_done = 1;
    }

    __half* d_wh  = nullptr;
    __half* d_wph = nullptr;
    cudaGetSymbolAddress((void**)&d_wh,  g_wh);
    cudaGetSymbolAddress((void**)&d_wph, g_wph);

    // main stream: x + qkv_w converts (needed by qkv gemm immediately)
    convert_x_kernel<<<2048, 256>>>(x);
    convert_w_kernel<<<432, 256>>>(qkv_w, CDIM * QKV_N / 4, d_wh);

    // fork side chain: proj weights + cpb + bm (independent of qkv gemm)
    cudaEventRecord(evFork, 0);
    cudaStreamWaitEvent(s2, evFork, 0);
    convert_w_kernel<<<144, 256, 0, s2>>>(proj_w, CDIM * CDIM / 4, d_wph);
    cpb_hidden_kernel<<<8192, 256, 0, s2>>>(rel_table, cpb_w1, cpb_b1);
    cpb_out_kernel<<<192, 256, 0, s2>>>(cpb_w2);
    cpb_gather_kernel<<<192, 256, 0, s2>>>(rel_index);
    bm_combine_kernel<<<49152, 256, 0, s2>>>(mask);
    cudaEventRecord(evJoin, s2);

    // qkv gemm overlaps the side chain
    {
        dim3 grid(QKV_N / 128, M1 / 128);
        hgemm_qkv<<<grid, 256, HGEMM_SMEM_BYTES>>>();
    }

    // join: attention needs g_bm (side chain) + g_qkv (main)
    cudaStreamWaitEvent(0, evJoin, 0);
    attn_kernel<<<NWIN * HEADS * 4, 256>>>(logit_scale, qkv_b);

    // proj gemm: [262144,384] x [384,384], fp16 in / fp32 accum
    {
        dim3 grid(CDIM / 128, M1 / 128);
        hgemm_proj<<<grid, 256, HGEMM_SMEM_BYTES>>>(proj_b, out);
    }
}

// round 17
// speedup vs baseline: 1.0265x; 1.0265x over previous
#include <cuda_runtime.h>
#include <cuda_fp16.h>
#include <cstdint>
#include <mma.h>
#include <math.h>

using namespace nvcuda;

// ---------------------------------------------------------------------------
// WindowAttentionV2: b=4096 windows, n=64 tokens, C=384, H=12 heads, d=32
// ---------------------------------------------------------------------------

#define BWIN   4096
#define NTOK   64
#define CDIM   384
#define HEADS  12
#define HDIM   32
#define NWIN   1024
#define M1     (BWIN * NTOK)          // 262144 rows
#define QKV_N  (3 * CDIM)             // 1152
#define QKV_STRIDE (BWIN * HEADS * NTOK * HDIM)

// Scratch (device globals; no allocations allowed)
__device__ __half g_qkv[3ll * QKV_STRIDE];          // fp16 [3][b][h][n][d] (no bias)
__device__ __half g_att[(long long)M1 * CDIM];      // fp16 attention output
__device__ __half g_xh[(long long)M1 * CDIM];       // fp16 copy of x
__device__ __half g_wh[CDIM * QKV_N];               // fp16 copy of qkv_w
__device__ __half g_wph[CDIM * CDIM];               // fp16 copy of proj_w
__device__ float  g_hidden[4096 * 512];             // cpb hidden layer
__device__ float  g_tab[4096 * HEADS];
__device__ float  g_bias[HEADS * NTOK * NTOK];
__device__ float  g_bm[(long long)HEADS * NWIN * NTOK * NTOK];  // bias+mask, 192MB

// ---------------------------------------------------------------------------
// Packed f32x2 helpers (sm_103a FFMA2 path — only reachable via PTX f32x2)
// ---------------------------------------------------------------------------
__device__ __forceinline__ unsigned long long pk2(float lo, float hi)
{
    unsigned long long r;
    asm("mov.b64 %0, {%1, %2};" : "=l"(r) : "r"(__float_as_uint(lo)), "r"(__float_as_uint(hi)));
    return r;
}
__device__ __forceinline__ float upk_sum(unsigned long long v)
{
    unsigned int lo, hi;
    asm("mov.b64 {%0, %1}, %2;" : "=r"(lo), "=r"(hi) : "l"(v));
    return __uint_as_float(lo) + __uint_as_float(hi);
}
#define FMA2(d, a, b, c) \
    asm("fma.rn.f32x2 %0, %1, %2, %3;" : "=l"(d) : "l"(a), "l"(b), "l"(c))

// Packed fp16 exp2: one MUFU.EX2.F16x2 evaluates two exponentials.
__device__ __forceinline__ float2 exp2_pair_h2(float ya, float yc)
{
    __half2 h = __floats2half2_rn(ya, yc);
    unsigned u = *reinterpret_cast<unsigned*>(&h);
    unsigned v;
    asm("ex2.approx.f16x2 %0, %1;" : "=r"(v) : "r"(u));
    __half2 r = *reinterpret_cast<__half2*>(&v);
    return __half22float2(r);
}

// ---------------------------------------------------------------------------
// CPB: hidden layer (4096x512 elementwise), then 4096x12 dot products
// ---------------------------------------------------------------------------
__global__ __launch_bounds__(256) void cpb_hidden_kernel(const float* __restrict__ table,
                                                         const float* __restrict__ w1,
                                                         const float* __restrict__ b1)
{
    int idx = blockIdx.x * blockDim.x + threadIdx.x;
    if (idx >= 4096 * 512) return;
    int i = idx >> 9;
    int j = idx & 511;
    float t0 = table[i * 2 + 0];
    float t1 = table[i * 2 + 1];
    g_hidden[idx] = fmaxf(fmaf(t0, w1[j], fmaf(t1, w1[512 + j], b1[j])), 0.f);
}

__global__ __launch_bounds__(256) void cpb_out_kernel(const float* __restrict__ w2)
{
    int e = blockIdx.x * blockDim.x + threadIdx.x;
    if (e >= 4096 * HEADS) return;
    int i = e / HEADS;
    int h = e - i * HEADS;
    const float* hid = &g_hidden[i * 512];
    float acc = 0.f;
    #pragma unroll 8
    for (int j = 0; j < 512; j++) acc += hid[j] * w2[j * HEADS + h];
    g_tab[e] = acc;
}

__global__ void cpb_gather_kernel(const int* __restrict__ index)
{
    int e = blockIdx.x * blockDim.x + threadIdx.x;
    if (e >= HEADS * 4096) return;
    int h = e / 4096;
    int qk = e % 4096;
    float v = g_tab[index[qk] * HEADS + h];
    g_bias[e] = 16.f / (1.f + expf(-v));
}

// bm[h][w][qk] = g_bias[h][qk] + mask[w][qk]
__global__ __launch_bounds__(256) void bm_combine_kernel(const float* __restrict__ mask)
{
    long long i = (long long)blockIdx.x * blockDim.x + threadIdx.x;   // float4 idx
    if (i >= (long long)HEADS * NWIN * 4096 / 4) return;
    long long f = i * 4;
    int h   = (int)(f >> 22);
    int w   = (int)((f >> 12) & (NWIN - 1));
    int qk4 = (int)(f & 4095);
    float4 bv = *(const float4*)&g_bias[h * 4096 + qk4];
    float4 mv = *(const float4*)&mask[(long long)w * 4096 + qk4];
    float4 o = make_float4(bv.x + mv.x, bv.y + mv.y, bv.z + mv.z, bv.w + mv.w);
    *(float4*)&g_bm[f] = o;
}

// ---------------------------------------------------------------------------
// fp32 -> fp16 converters
// ---------------------------------------------------------------------------
__global__ __launch_bounds__(256) void convert_x_kernel(const float* __restrict__ x)
{
    long long n4 = (long long)M1 * CDIM / 4;
    long long stride = (long long)gridDim.x * blockDim.x;
    for (long long i = blockIdx.x * blockDim.x + threadIdx.x; i < n4; i += stride) {
        float4 v = ((const float4*)x)[i];
        __half2* dst = (__half2*)g_xh;
        dst[2 * i + 0] = __floats2half2_rn(v.x, v.y);
        dst[2 * i + 1] = __floats2half2_rn(v.z, v.w);
    }
}

__global__ __launch_bounds__(256) void convert_w_kernel(const float* __restrict__ w,
                                                        int n4, __half* dst_h)
{
    int i = blockIdx.x * blockDim.x + threadIdx.x;
    if (i >= n4) return;
    float4 v = ((const float4*)w)[i];
    __half2* dst = (__half2*)dst_h;
    dst[2 * i + 0] = __floats2half2_rn(v.x, v.y);
    dst[2 * i + 1] = __floats2half2_rn(v.z, v.w);
}

// ---------------------------------------------------------------------------
// fp16 GEMM cores: 128x128 tile, BK=32, 3-stage cp.async ring (56.8 KB smem
// -> 3-4 blocks/SM co-resident vs 2 with 4 stages), fp32 accum.
// ---------------------------------------------------------------------------
#define HBK 32
#define HAPAD 40
#define HBPAD 136
#define HAS_STAGE (128 * HAPAD)
#define HBS_STAGE (HBK * HBPAD)
#define HSTAGES 3
#define HGEMM_SMEM_BYTES (HSTAGES * (HAS_STAGE + HBS_STAGE) * 2)   // 56832

__device__ __forceinline__ void cp16(void* s, const void* g)
{
    unsigned int sa = (unsigned int)__cvta_generic_to_shared(s);
    asm volatile("cp.async.cg.shared.global [%0], [%1], 16;\n" :: "r"(sa), "l"(g));
}

// qkv: A = g_xh, B = g_wh, N=1152; fp16 epilogue store into g_qkv
__global__ __launch_bounds__(256)
void hgemm_qkv()
{
    extern __shared__ __half hsm[];
    __half* As = hsm;
    __half* Bs = hsm + HSTAGES * HAS_STAGE;

    const int N = QKV_N, K = CDIM;
    int tid  = threadIdx.x;
    int lane = tid & 31;
    int warp = tid >> 5;
    int wm = warp >> 1;
    int wn = warp & 1;
    long long crow = (long long)blockIdx.y * 128;
    int ccol = blockIdx.x * 128;

    int ar[2], ac[2], br[2], bc[2];
    #pragma unroll
    for (int s = 0; s < 2; s++) {
        int i = tid + s * 256;
        ar[s] = i >> 2;  ac[s] = (i & 3) * 8;
        br[s] = i >> 4;  bc[s] = (i & 15) * 8;
    }

    wmma::fragment<wmma::accumulator, 16, 16, 16, float> acc[2][4];
    #pragma unroll
    for (int i = 0; i < 2; i++)
        #pragma unroll
        for (int j = 0; j < 4; j++) wmma::fill_fragment(acc[i][j], 0.f);

    const int NK = K / HBK;   // 12

    auto issue = [&](int buf, int kt) {
        int k0 = kt * HBK;
        #pragma unroll
        for (int s = 0; s < 2; s++) {
            cp16(&As[buf * HAS_STAGE + ar[s] * HAPAD + ac[s]],
                 g_xh + (crow + ar[s]) * K + k0 + ac[s]);
            cp16(&Bs[buf * HBS_STAGE + br[s] * HBPAD + bc[s]],
                 g_wh + (long long)(k0 + br[s]) * N + ccol + bc[s]);
        }
        asm volatile("cp.async.commit_group;\n");
    };

    issue(0, 0); issue(1, 1);

    int buf = 0;
    for (int kt = 0; kt < NK; kt++) {
        if (kt < NK - 1) asm volatile("cp.async.wait_group 1;\n");
        else             asm volatile("cp.async.wait_group 0;\n");
        __syncthreads();
        if (kt + 2 < NK) {
            int nb = buf + 2; if (nb >= 3) nb -= 3;
            issue(nb, kt + 2);
        }

        __half* Ab = &As[buf * HAS_STAGE];
        __half* Bb = &Bs[buf * HBS_STAGE];
        #pragma unroll
        for (int kk = 0; kk < HBK; kk += 16) {
            wmma::fragment<wmma::matrix_a, 16, 16, 16, __half, wmma::row_major> af[2];
            wmma::fragment<wmma::matrix_b, 16, 16, 16, __half, wmma::row_major> bf[4];
            #pragma unroll
            for (int i = 0; i < 2; i++)
                wmma::load_matrix_sync(af[i], &Ab[(wm * 32 + i * 16) * HAPAD + kk], HAPAD);
            #pragma unroll
            for (int j = 0; j < 4; j++)
                wmma::load_matrix_sync(bf[j], &Bb[kk * HBPAD + wn * 64 + j * 16], HBPAD);
            #pragma unroll
            for (int i = 0; i < 2; i++)
                #pragma unroll
                for (int j = 0; j < 4; j++)
                    wmma::mma_sync(acc[i][j], af[i], bf[j], acc[i][j]);
        }
        if (++buf == 3) buf = 0;
    }

    // fp16 epilogue via per-warp smem patch (stage buffers are dead)
    __syncthreads();
    float* ep = ((float*)hsm) + warp * 256;
    #pragma unroll
    for (int i = 0; i < 2; i++) {
        long long m0 = crow + wm * 32 + i * 16;
        int b  = (int)(m0 >> 6);
        int n0 = (int)(m0 & 63);
        #pragma unroll
        for (int j = 0; j < 4; j++) {
            int c0 = ccol + wn * 64 + j * 16;
            int three = c0 / CDIM;
            int rem   = c0 - three * CDIM;
            int head  = rem >> 5;
            int dd0   = rem & 31;
            long long off = (long long)three * QKV_STRIDE +
                            (((long long)(b * HEADS + head)) * NTOK + n0) * HDIM + dd0;
            wmma::store_matrix_sync(ep, acc[i][j], 16, wmma::mem_row_major);
            __syncwarp();
            #pragma unroll
            for (int e = 0; e < 4; e++) {
                int idx = lane + e * 32;          // 0..127 pair index
                int r  = idx >> 3;                // 0..15
                int c2 = idx & 7;                 // 0..7 pairs
                float2 v = ((const float2*)ep)[idx];
                *(__half2*)&g_qkv[off + r * HDIM + 2 * c2] =
                    __floats2half2_rn(v.x, v.y);
            }
            __syncwarp();
        }
    }
}

// proj: A = g_att (half), B = g_wph, N=384; +bias, fp32 dense out
__global__ __launch_bounds__(256)
void hgemm_proj(const float* __restrict__ bias, float* __restrict__ Cout)
{
    extern __shared__ __half hsm[];
    __half* As = hsm;
    __half* Bs = hsm + HSTAGES * HAS_STAGE;

    const int N = CDIM, K = CDIM;
    int tid  = threadIdx.x;
    int lane = tid & 31;
    int warp = tid >> 5;
    int wm = warp >> 1;
    int wn = warp & 1;
    long long crow = (long long)blockIdx.y * 128;
    int ccol = blockIdx.x * 128;

    int ar[2], ac[2], br[2], bc[2];
    #pragma unroll
    for (int s = 0; s < 2; s++) {
        int i = tid + s * 256;
        ar[s] = i >> 2;  ac[s] = (i & 3) * 8;
        br[s] = i >> 4;  bc[s] = (i & 15) * 8;
    }

    wmma::fragment<wmma::accumulator, 16, 16, 16, float> acc[2][4];
    #pragma unroll
    for (int i = 0; i < 2; i++)
        #pragma unroll
        for (int j = 0; j < 4; j++) wmma::fill_fragment(acc[i][j], 0.f);

    const int NK = K / HBK;

    auto issue = [&](int buf, int kt) {
        int k0 = kt * HBK;
        #pragma unroll
        for (int s = 0; s < 2; s++) {
            cp16(&As[buf * HAS_STAGE + ar[s] * HAPAD + ac[s]],
                 g_att + (crow + ar[s]) * K + k0 + ac[s]);
            cp16(&Bs[buf * HBS_STAGE + br[s] * HBPAD + bc[s]],
                 g_wph + (long long)(k0 + br[s]) * N + ccol + bc[s]);
        }
        asm volatile("cp.async.commit_group;\n");
    };

    issue(0, 0); issue(1, 1);

    int buf = 0;
    for (int kt = 0; kt < NK; kt++) {
        if (kt < NK - 1) asm volatile("cp.async.wait_group 1;\n");
        else             asm volatile("cp.async.wait_group 0;\n");
        __syncthreads();
        if (kt + 2 < NK) {
            int nb = buf + 2; if (nb >= 3) nb -= 3;
            issue(nb, kt + 2);
        }

        __half* Ab = &As[buf * HAS_STAGE];
        __half* Bb = &Bs[buf * HBS_STAGE];
        #pragma unroll
        for (int kk = 0; kk < HBK; kk += 16) {
            wmma::fragment<wmma::matrix_a, 16, 16, 16, __half, wmma::row_major> af[2];
            wmma::fragment<wmma::matrix_b, 16, 16, 16, __half, wmma::row_major> bf[4];
            #pragma unroll
            for (int i = 0; i < 2; i++)
                wmma::load_matrix_sync(af[i], &Ab[(wm * 32 + i * 16) * HAPAD + kk], HAPAD);
            #pragma unroll
            for (int j = 0; j < 4; j++)
                wmma::load_matrix_sync(bf[j], &Bb[kk * HBPAD + wn * 64 + j * 16], HBPAD);
            #pragma unroll
            for (int i = 0; i < 2; i++)
                #pragma unroll
                for (int j = 0; j < 4; j++)
                    wmma::mma_sync(acc[i][j], af[i], bf[j], acc[i][j]);
        }
        if (++buf == 3) buf = 0;
    }

    __syncthreads();
    float* ep = ((float*)hsm) + warp * 256;
    #pragma unroll
    for (int i = 0; i < 2; i++) {
        #pragma unroll
        for (int j = 0; j < 4; j++) {
            wmma::store_matrix_sync(ep, acc[i][j], 16, wmma::mem_row_major);
            __syncwarp();
            long long m0 = crow + wm * 32 + i * 16;
            int c0 = ccol + wn * 64 + j * 16;
            #pragma unroll
            for (int e = 0; e < 8; e++) {
                int idx = lane + e * 32;
                int r = idx >> 4;
                int c = idx & 15;
                Cout[(m0 + r) * N + c0 + c] = ep[idx] + bias[c0 + c];
            }
            __syncwarp();
        }
    }
}

// ---------------------------------------------------------------------------
// Fused attention — R13 exactly (best-known configuration; original block
// order, fp32 smem, FFMA2, packed exp, bm preloaded coalesced into sc).
// One block per (b,h), 256 threads.
// ---------------------------------------------------------------------------
#define QKS 34
#define SCS 68

__global__ __launch_bounds__(256)
void attn_kernel(const float* __restrict__ logit_scale,
                 const float* __restrict__ qkv_b)
{
    int bh = blockIdx.x;
    int b = bh / HEADS;
    int h = bh - b * HEADS;

    __shared__ float qs[64 * QKS];
    __shared__ float ks[64 * QKS];
    __shared__ float vs[64 * 33];
    __shared__ float sc[64 * SCS];
    __shared__ float rq[64];
    __shared__ float rk[64];

    int tid  = threadIdx.x;
    int warp = tid >> 5;
    int lane = tid & 31;
    int tr = tid >> 4;
    int tc = tid & 15;

    const __half* qg = g_qkv + (long long)bh * (NTOK * HDIM);
    const __half* kg = qg + QKV_STRIDE;
    const __half* vg = kg + QKV_STRIDE;

    int w = b & (NWIN - 1);
    const float* bmrow = g_bm + ((long long)h * NWIN + w) * 4096;

    // stream bias+mask row into sc (coalesced float4; latency overlapped)
    #pragma unroll
    for (int k = 0; k < 4; k++) {
        int e4 = tid + k * 256;          // float4 index 0..1023
        int qi  = e4 >> 4;
        int kj4 = (e4 & 15) * 4;
        float4 v = ((const float4*)bmrow)[e4];
        *(float4*)&sc[qi * SCS + kj4] = v;
    }

    // per-thread column-group biases: 8 columns starting at cb
    int cb = (tid & 3) * 8;
    float bq8[8], bk8[8], bv8[8];
    #pragma unroll
    for (int t = 0; t < 8; t++) {
        bq8[t] = qkv_b[h * HDIM + cb + t];
        bk8[t] = qkv_b[CDIM + h * HDIM + cb + t];
        bv8[t] = qkv_b[2 * CDIM + h * HDIM + cb + t];
    }

    {
        int e = tid;               // 0..255 : 16B (8 halves) per tensor
        int r = e >> 2;            // row 0..63
        int c = (e & 3) * 8;       // col 0,8,16,24
        uint4 qraw = ((const uint4*)qg)[e];
        uint4 kraw = ((const uint4*)kg)[e];
        uint4 vraw = ((const uint4*)vg)[e];
        const __half2* qh = (const __half2*)&qraw;
        const __half2* kh = (const __half2*)&kraw;
        const __half2* vh = (const __half2*)&vraw;
        float* dq = &qs[r * QKS + c];
        float* dk = &ks[r * QKS + c];
        float* dv = &vs[r * 33 + c];
        #pragma unroll
        for (int t = 0; t < 4; t++) {
            float2 qf = __half22float2(qh[t]);
            float2 kf = __half22float2(kh[t]);
            float2 vf = __half22float2(vh[t]);
            dq[2 * t]     = qf.x + bq8[2 * t];
            dq[2 * t + 1] = qf.y + bq8[2 * t + 1];
            dk[2 * t]     = kf.x + bk8[2 * t];
            dk[2 * t + 1] = kf.y + bk8[2 * t + 1];
            dv[2 * t]     = vf.x + bv8[2 * t];
            dv[2 * t + 1] = vf.y + bv8[2 * t + 1];
        }
    }
    __syncthreads();

    // per-row inverse norms (no element writeback)
    #pragma unroll
    for (int i = 0; i < 16; i++) {
        int r = warp * 16 + i;
        const float* buf = (r < 64) ? &qs[r * QKS] : &ks[(r - 64) * QKS];
        float v = buf[lane];
        float ss = v * v;
        #pragma unroll
        for (int o = 16; o; o >>= 1) ss += __shfl_xor_sync(~0u, ss, o);
        if (lane == 0) {
            float inv = 1.f / fmaxf(sqrtf(ss), 1e-12f);
            if (r < 64) rq[r] = inv; else rk[r - 64] = inv;
        }
    }
    __syncthreads();

    float scale = expf(fminf(logit_scale[h], 4.60517018598809f)); // ln(100)

    // scores: 4x4 register tile, packed f32x2 FMA along l; bm base in sc
    {
        unsigned long long acc2[4][4];
        #pragma unroll
        for (int i = 0; i < 4; i++)
            #pragma unroll
            for (int j = 0; j < 4; j++) acc2[i][j] = 0ull;
        #pragma unroll 4
        for (int l2 = 0; l2 < 16; l2++) {
            unsigned long long qv[4], kv[4];
            #pragma unroll
            for (int i = 0; i < 4; i++)
                qv[i] = *(const unsigned long long*)&qs[(tr + 16 * i) * QKS + 2 * l2];
            #pragma unroll
            for (int j = 0; j < 4; j++)
                kv[j] = *(const unsigned long long*)&ks[(tc + 16 * j) * QKS + 2 * l2];
            #pragma unroll
            for (int i = 0; i < 4; i++)
                #pragma unroll
                for (int j = 0; j < 4; j++)
                    FMA2(acc2[i][j], qv[i], kv[j], acc2[i][j]);
        }
        #pragma unroll
        for (int i = 0; i < 4; i++) {
            int qi = tr + 16 * i;
            float si = scale * rq[qi];
            #pragma unroll
            for (int j = 0; j < 4; j++) {
                int kj = tc + 16 * j;
                float s = si * rk[kj];
                float base = sc[qi * SCS + kj];
                sc[qi * SCS + kj] = fmaf(upk_sum(acc2[i][j]), s, base);
            }
        }
    }
    __syncthreads();

    // softmax: warp per 8 rows; exp via packed fp16 MUFU (2 exps / MUFU)
    {
        const float L2E = 1.44269504088896f;
        #pragma unroll
        for (int i = 0; i < 8; i++) {
            int qi = warp * 8 + i;
            float a = sc[qi * SCS + lane];
            float c = sc[qi * SCS + 32 + lane];
            float mx = fmaxf(a, c);
            #pragma unroll
            for (int o = 16; o; o >>= 1) mx = fmaxf(mx, __shfl_xor_sync(~0u, mx, o));
            float2 e = exp2_pair_h2((a - mx) * L2E, (c - mx) * L2E);
            float sm = e.x + e.y;
            #pragma unroll
            for (int o = 16; o; o >>= 1) sm += __shfl_xor_sync(~0u, sm, o);
            float inv = 1.f / sm;
            sc[qi * SCS + lane]      = e.x * inv;
            sc[qi * SCS + 32 + lane] = e.y * inv;
        }
    }
    __syncthreads();

    // PV: 4x2 register tile, packed f32x2 FMA along kj
    {
        unsigned long long acc2[4][2];
        #pragma unroll
        for (int i = 0; i < 4; i++) { acc2[i][0] = 0ull; acc2[i][1] = 0ull; }
        #pragma unroll 4
        for (int kj2 = 0; kj2 < 32; kj2++) {
            unsigned long long pv[4];
            #pragma unroll
            for (int i = 0; i < 4; i++)
                pv[i] = *(const unsigned long long*)&sc[(tr + 16 * i) * SCS + 2 * kj2];
            unsigned long long vv0 = pk2(vs[(2 * kj2) * 33 + tc],
                                         vs[(2 * kj2 + 1) * 33 + tc]);
            unsigned long long vv1 = pk2(vs[(2 * kj2) * 33 + tc + 16],
                                         vs[(2 * kj2 + 1) * 33 + tc + 16]);
            #pragma unroll
            for (int i = 0; i < 4; i++) {
                FMA2(acc2[i][0], pv[i], vv0, acc2[i][0]);
                FMA2(acc2[i][1], pv[i], vv1, acc2[i][1]);
            }
        }
        #pragma unroll
        for (int i = 0; i < 4; i++) {
            int qi = tr + 16 * i;
            long long rowo = ((long long)b * NTOK + qi) * CDIM + h * HDIM;
            g_att[rowo + tc]      = __float2half_rn(upk_sum(acc2[i][0]));
            g_att[rowo + tc + 16] = __float2half_rn(upk_sum(acc2[i][1]));
        }
    }
}

// ---------------------------------------------------------------------------
extern "C" void kernel_launch(void* const* d_in, const int* in_sizes, int n_in,
                              void* d_out, int out_size)
{
    const float* x           = (const float*)d_in[0];
    const float* mask        = (const float*)d_in[1];
    const float* qkv_w       = (const float*)d_in[2];
    const float* qkv_b       = (const float*)d_in[3];
    const float* proj_w      = (const float*)d_in[4];
    const float* proj_b      = (const float*)d_in[5];
    const float* logit_scale = (const float*)d_in[6];
    const float* cpb_w1      = (const float*)d_in[7];
    const float* cpb_b1      = (const float*)d_in[8];
    const float* cpb_w2      = (const float*)d_in[9];
    const float* rel_table   = (const float*)d_in[10];
    const int*   rel_index   = (const int*)d_in[11];
    float* out = (float*)d_out;

    static int attr_done = 0;
    if (!attr_done) {
        cudaFuncSetAttribute(hgemm_qkv,  cudaFuncAttributeMaxDynamicSharedMemorySize, HGEMM_SMEM_BYTES);
        cudaFuncSetAttribute(hgemm_proj, cudaFuncAttributeMaxDynamicSharedMemorySize, HGEMM_SMEM_BYTES);
        attr_done = 1;
    }

    __half* d_wh  = nullptr;
    __half* d_wph = nullptr;
    cudaGetSymbolAddress((void**)&d_wh,  g_wh);
    cudaGetSymbolAddress((void**)&d_wph, g_wph);

    convert_x_kernel<<<2048, 256>>>(x);
    convert_w_kernel<<<432, 256>>>(qkv_w, CDIM * QKV_N / 4, d_wh);
    convert_w_kernel<<<144, 256>>>(proj_w, CDIM * CDIM / 4, d_wph);

    cpb_hidden_kernel<<<8192, 256>>>(rel_table, cpb_w1, cpb_b1);
    cpb_out_kernel<<<192, 256>>>(cpb_w2);
    cpb_gather_kernel<<<192, 256>>>(rel_index);
    bm_combine_kernel<<<49152, 256>>>(mask);

    // qkv gemm: [262144,384] x [384,1152], fp16 in / fp32 accum / fp16 out
    {
        dim3 grid(QKV_N / 128, M1 / 128);
        hgemm_qkv<<<grid, 256, HGEMM_SMEM_BYTES>>>();
    }

    attn_kernel<<<BWIN * HEADS, 256>>>(logit_scale, qkv_b);

    // proj gemm: [262144,384] x [384,384], fp16 in / fp32 accum
    {
        dim3 grid(CDIM / 128, M1 / 128);
        hgemm_proj<<<grid, 256, HGEMM_SMEM_BYTES>>>(proj_b, out);
    }
}